// round 13
// baseline (speedup 1.0000x reference)
#include <cuda_runtime.h>
#include <cuda_bf16.h>
#include <cstdint>

#define B_   4
#define T_   2048
#define D_   2048
#define H_   16
#define HD_  128
#define NTOK (B_*T_)
#define NELEM ((size_t)NTOK*D_)
#define WELEM ((size_t)D_*D_)

// log2(e)/sqrt(128): folded into Q so softmax uses exp2
#define QSCALE 0.12751743f

// ---------------- device scratch ----------------
__device__ __nv_bfloat16 g_xhi[NELEM];
__device__ __nv_bfloat16 g_xlo[NELEM];
__device__ __nv_bfloat16 g_qh [NELEM];
__device__ __nv_bfloat16 g_ql [NELEM];
__device__ __nv_bfloat16 g_kh [NELEM];
__device__ __nv_bfloat16 g_kl [NELEM];
__device__ __nv_bfloat16 g_vh [NELEM];
__device__ __nv_bfloat16 g_vl [NELEM];
__device__ __nv_bfloat16 g_aohi[NELEM];
__device__ __nv_bfloat16 g_aolo[NELEM];
__device__ __nv_bfloat16 g_wth[4*WELEM];   // transposed hi: [which][N][K]
__device__ __nv_bfloat16 g_wtl[4*WELEM];   // transposed lo

// ---------------- PTX helpers (compute_103-safe) ----------------
__device__ __forceinline__ uint32_t smem_u32(const void* p) {
    uint32_t a;
    asm("{ .reg .u64 t; cvta.to.shared.u64 t, %1; cvt.u32.u64 %0, t; }" : "=r"(a) : "l"(p));
    return a;
}
__device__ __forceinline__ void cp16(uint32_t sa, const void* ga) {
    asm volatile("cp.async.cg.shared.global [%0], [%1], 16;" :: "r"(sa), "l"(ga));
}
__device__ __forceinline__ void cp_commit() {
    asm volatile("cp.async.commit_group;" ::: "memory");
}
template <int N>
__device__ __forceinline__ void cp_wait() {
    asm volatile("cp.async.wait_group %0;" :: "n"(N) : "memory");
}
__device__ __forceinline__ void ldsm4(uint32_t* r, uint32_t addr) {
    asm volatile("ldmatrix.sync.aligned.m8n8.x4.shared.b16 {%0,%1,%2,%3}, [%4];"
                 : "=r"(r[0]), "=r"(r[1]), "=r"(r[2]), "=r"(r[3]) : "r"(addr));
}
__device__ __forceinline__ void ldsm4t(uint32_t* r, uint32_t addr) {
    asm volatile("ldmatrix.sync.aligned.m8n8.x4.trans.shared.b16 {%0,%1,%2,%3}, [%4];"
                 : "=r"(r[0]), "=r"(r[1]), "=r"(r[2]), "=r"(r[3]) : "r"(addr));
}
__device__ __forceinline__ void mma_bf16(float* d, const uint32_t* a, uint32_t b0, uint32_t b1) {
    asm volatile("mma.sync.aligned.m16n8k16.row.col.f32.bf16.bf16.f32 "
                 "{%0,%1,%2,%3}, {%4,%5,%6,%7}, {%8,%9}, {%0,%1,%2,%3};"
                 : "+f"(d[0]), "+f"(d[1]), "+f"(d[2]), "+f"(d[3])
                 : "r"(a[0]), "r"(a[1]), "r"(a[2]), "r"(a[3]), "r"(b0), "r"(b1));
}
// split (x,y) -> packed bf16x2 hi and lo residual (x -> low half)
__device__ __forceinline__ void split_pack(float x, float y, uint32_t& h, uint32_t& l) {
    __nv_bfloat16 hx = __float2bfloat16(x), hy = __float2bfloat16(y);
    float rx = x - __bfloat162float(hx), ry = y - __bfloat162float(hy);
    __nv_bfloat162 hh; hh.x = hx; hh.y = hy;
    __nv_bfloat162 ll = __float22bfloat162_rn(make_float2(rx, ry));
    h = *reinterpret_cast<uint32_t*>(&hh);
    l = *reinterpret_cast<uint32_t*>(&ll);
}

// ---------------- fp32 -> bf16 hi/lo split of x ----------------
__device__ __forceinline__ void split1(float v, __nv_bfloat16& h, __nv_bfloat16& l) {
    h = __float2bfloat16(v);
    l = __float2bfloat16(v - __bfloat162float(h));
}
__global__ void fsplit_x(const float* __restrict__ in) {
    size_t i = (size_t)(blockIdx.x * blockDim.x + threadIdx.x) * 4;
    float4 v = *reinterpret_cast<const float4*>(in + i);
    __nv_bfloat16 h0,h1,h2,h3,l0,l1,l2,l3;
    split1(v.x,h0,l0); split1(v.y,h1,l1); split1(v.z,h2,l2); split1(v.w,h3,l3);
    __nv_bfloat162* hp = reinterpret_cast<__nv_bfloat162*>(g_xhi + i);
    __nv_bfloat162* lp = reinterpret_cast<__nv_bfloat162*>(g_xlo + i);
    __nv_bfloat162 a; a.x=h0; a.y=h1; hp[0]=a; a.x=h2; a.y=h3; hp[1]=a;
    __nv_bfloat162 b; b.x=l0; b.y=l1; lp[0]=b; b.x=l2; b.y=l3; lp[1]=b;
}

// ---------------- weight transpose + split: W[K,N] -> Wt hi/lo [N,K] ----------------
__global__ void wsplit(const float* __restrict__ Wq, const float* __restrict__ Wk,
                       const float* __restrict__ Wv, const float* __restrict__ Wo) {
    const float* W;
    int z = blockIdx.z;
    if (z == 0) W = Wq; else if (z == 1) W = Wk; else if (z == 2) W = Wv; else W = Wo;
    __nv_bfloat16* th = g_wth + (size_t)z * WELEM;
    __nv_bfloat16* tl = g_wtl + (size_t)z * WELEM;

    __shared__ float t[32][33];
    int tx = threadIdx.x & 31, ty = threadIdx.x >> 5;   // 32 x 8
    int x0 = blockIdx.x * 32, y0 = blockIdx.y * 32;
#pragma unroll
    for (int i = 0; i < 4; i++)
        t[ty + 8*i][tx] = W[(size_t)(y0 + ty + 8*i) * D_ + x0 + tx];
    __syncthreads();
#pragma unroll
    for (int i = 0; i < 4; i++) {
        int n = x0 + ty + 8*i, k = y0 + tx;
        float v = t[tx][ty + 8*i];
        __nv_bfloat16 h, l;
        split1(v, h, l);
        th[(size_t)n * D_ + k] = h;
        tl[(size_t)n * D_ + k] = l;
    }
}

// ---------------- HMMA GEMM core (2 CTAs/SM) — R12-proven ----------------
// C[128,128] = (Ah+Al)[128,2048] @ (Bh+Bl)t ; 256 thr, 8 warps (4x2), warp 32x64.
// BK=32, stride 80B (conflict-free ldmatrix), 2-stage cp.async.
#define GST_B    80
#define GTILE_B  (128*GST_B)              // 10240
#define GSTAGE_B (4*GTILE_B)              // 40960 (Ah, Al, Bh, Bl)
#define GSMEM_TOT (2*GSTAGE_B)            // 81920 -> 2 CTAs/SM

__device__ __forceinline__
void gemm_hmma_core(const __nv_bfloat16* __restrict__ Ah, const __nv_bfloat16* __restrict__ Al,
                    const __nv_bfloat16* __restrict__ Bh, const __nv_bfloat16* __restrict__ Bl,
                    float* __restrict__ Cf, const float* __restrict__ bias,
                    __nv_bfloat16* __restrict__ oh, __nv_bfloat16* __restrict__ ol, float oscale,
                    int bx, int by)
{
    extern __shared__ char smem[];
    const uint32_t sb = smem_u32(smem);
    const int tid = threadIdx.x;
    const int wid = tid >> 5, l = tid & 31;
    const int wm = wid >> 1, wn = wid & 1;     // 4 x 2 warps, warp tile 32(m) x 64(n)
    const int m0 = by * 128, n0 = bx * 128;

    const __nv_bfloat16* src[4] = {
        Ah + (size_t)m0 * D_, Al + (size_t)m0 * D_,
        Bh + (size_t)n0 * D_, Bl + (size_t)n0 * D_ };

    // ldmatrix lane addressing
    const int a_row = (l & 7) + ((l >> 3) & 1) * 8;
    const int a_c16 = ((l >> 4) & 1) * 16;
    const int b_row = (l & 7) + ((l >> 4) & 1) * 8;
    const int b_c16 = ((l >> 3) & 1) * 16;
    uint32_t aoff[2], boff[4];
#pragma unroll
    for (int i = 0; i < 2; i++) aoff[i] = (32*wm + 16*i + a_row) * GST_B + a_c16;
#pragma unroll
    for (int p = 0; p < 4; p++) boff[p] = (64*wn + 16*p + b_row) * GST_B + b_c16;

    float d[2][8][4];
#pragma unroll
    for (int i = 0; i < 2; i++)
#pragma unroll
        for (int j = 0; j < 8; j++)
#pragma unroll
            for (int q = 0; q < 4; q++) d[i][j][q] = 0.f;

    auto issue = [&](int ch) {
        const uint32_t s0 = sb + (ch & 1) * GSTAGE_B;
        const int k0 = ch * 32;
#pragma unroll
        for (int a = 0; a < 4; a++) {
#pragma unroll
            for (int it = 0; it < 2; it++) {
                int idx = tid + it * 256;
                int row = idx >> 2, c = idx & 3;
                cp16(s0 + a*GTILE_B + row*GST_B + c*16,
                     src[a] + (size_t)row * D_ + k0 + c*8);
            }
        }
        cp_commit();
    };

    issue(0);
#pragma unroll 1
    for (int ch = 0; ch < 64; ch++) {
        if (ch < 63) { issue(ch + 1); cp_wait<1>(); }
        else         { cp_wait<0>(); }
        __syncthreads();

        const uint32_t s0 = sb + (ch & 1) * GSTAGE_B;
#pragma unroll
        for (int ks = 0; ks < 2; ks++) {
            const int kb = ks * 32;   // 16 bf16 * 2B
            uint32_t AH[2][4], AL[2][4];
#pragma unroll
            for (int i = 0; i < 2; i++) {
                ldsm4(AH[i], s0 +           aoff[i] + kb);
                ldsm4(AL[i], s0 + GTILE_B + aoff[i] + kb);
            }
#pragma unroll
            for (int p = 0; p < 4; p++) {
                uint32_t BH[4], BL[4];
                ldsm4(BH, s0 + 2*GTILE_B + boff[p] + kb);
                ldsm4(BL, s0 + 3*GTILE_B + boff[p] + kb);
#pragma unroll
                for (int i = 0; i < 2; i++) {
                    mma_bf16(d[i][2*p],   AH[i], BH[0], BH[1]);
                    mma_bf16(d[i][2*p],   AH[i], BL[0], BL[1]);
                    mma_bf16(d[i][2*p],   AL[i], BH[0], BH[1]);
                    mma_bf16(d[i][2*p+1], AH[i], BH[2], BH[3]);
                    mma_bf16(d[i][2*p+1], AH[i], BL[2], BL[3]);
                    mma_bf16(d[i][2*p+1], AL[i], BH[2], BH[3]);
                }
            }
        }
        __syncthreads();
    }

    const int gid = l >> 2, tig = l & 3;
#pragma unroll
    for (int i = 0; i < 2; i++) {
#pragma unroll
        for (int j = 0; j < 8; j++) {
            int row = m0 + 32*wm + 16*i + gid;
            int col = n0 + 64*wn + 8*j + 2*tig;
            if (Cf) {
                float2 v0 = make_float2(d[i][j][0], d[i][j][1]);
                float2 v1 = make_float2(d[i][j][2], d[i][j][3]);
                const float2 bb = *reinterpret_cast<const float2*>(bias + col);
                v0.x += bb.x; v0.y += bb.y;
                v1.x += bb.x; v1.y += bb.y;
                *reinterpret_cast<float2*>(Cf + (size_t)row * D_ + col)       = v0;
                *reinterpret_cast<float2*>(Cf + (size_t)(row + 8) * D_ + col) = v1;
            } else {
                uint32_t hh, ll;
                split_pack(d[i][j][0]*oscale, d[i][j][1]*oscale, hh, ll);
                *reinterpret_cast<uint32_t*>(oh + (size_t)row * D_ + col) = hh;
                *reinterpret_cast<uint32_t*>(ol + (size_t)row * D_ + col) = ll;
                split_pack(d[i][j][2]*oscale, d[i][j][3]*oscale, hh, ll);
                *reinterpret_cast<uint32_t*>(oh + (size_t)(row + 8) * D_ + col) = hh;
                *reinterpret_cast<uint32_t*>(ol + (size_t)(row + 8) * D_ + col) = ll;
            }
        }
    }
}

__global__ __launch_bounds__(256, 2)
void gemm_qkv_tc() {
    const int z = blockIdx.z;
    __nv_bfloat16 *oh, *ol; float sc;
    if (z == 0)      { oh = g_qh; ol = g_ql; sc = QSCALE; }
    else if (z == 1) { oh = g_kh; ol = g_kl; sc = 1.f; }
    else             { oh = g_vh; ol = g_vl; sc = 1.f; }
    gemm_hmma_core(g_xhi, g_xlo, g_wth + (size_t)z * WELEM, g_wtl + (size_t)z * WELEM,
                   nullptr, nullptr, oh, ol, sc, blockIdx.x, blockIdx.y);
}
__global__ __launch_bounds__(256, 2)
void gemm_out_tc(const float* __restrict__ bo, float* __restrict__ out) {
    gemm_hmma_core(g_aohi, g_aolo, g_wth + 3 * WELEM, g_wtl + 3 * WELEM,
                   out, bo, nullptr, nullptr, 1.f, blockIdx.x, blockIdx.y);
}

// ---------------- HMMA flash attention (causal), 2 CTAs/SM ----------------
// CTA: 64 q-rows x one head. 4 warps (warp = m16). BN=32 keys/iter.
// 2-stage cp.async KV (Kh,Kl,Vh,Vl). Softmax in fragments (exp2; scale folded into Q).
// smem 104448 B -> 2 CTAs/SM for decoupled softmax/MMA overlap.
#define AST       272                      // smem row stride bytes (conflict-free ldmatrix)
#define AQ_TILE_B (64*AST)                 // 17408
#define AKV_TILE_B (32*AST)                // 8704
#define AKV_STAGE_B (4*AKV_TILE_B)         // 34816
#define ASMEM_TOT (2*AQ_TILE_B + 2*AKV_STAGE_B)   // 104448

__global__ __launch_bounds__(128, 2)
void attn_hmma()
{
    extern __shared__ char smem[];
    const uint32_t sb = smem_u32(smem);
    const int tid = threadIdx.x;
    const int wid = tid >> 5, l = tid & 31;
    const int g = l >> 2, t = l & 3;

    const int bid = blockIdx.x;
    const int qb = 31 - (bid >> 6);        // heavy tiles first (64-row q tiles)
    const int bh = bid & 63;
    const int b = bh >> 4, h = bh & 15;
    const int q0 = qb * 64;
    const int nkb = 2*qb + 2;              // BN=32 key blocks
    const size_t qbase = ((size_t)(b*T_ + q0)) * D_ + h * HD_;
    const size_t kbase = ((size_t)(b*T_)) * D_ + h * HD_;

    const uint32_t sQh = sb, sQl = sb + AQ_TILE_B;
    const uint32_t sKV = sb + 2*AQ_TILE_B;

    // Q tiles (hi/lo) via cp.async; joins first commit group
#pragma unroll
    for (int i = 0; i < 8; i++) {
        int idx = tid + i*128;
        int r = idx >> 4, c = idx & 15;
        cp16(sQh + r*AST + c*16, g_qh + qbase + (size_t)r * D_ + c*8);
        cp16(sQl + r*AST + c*16, g_ql + qbase + (size_t)r * D_ + c*8);
    }

    auto issue = [&](int kb) {
        const uint32_t s0 = sKV + (kb & 1) * AKV_STAGE_B;
        const size_t koff = kbase + (size_t)kb * 32 * D_;
        const __nv_bfloat16* srcs[4] = { g_kh + koff, g_kl + koff, g_vh + koff, g_vl + koff };
#pragma unroll
        for (int a = 0; a < 4; a++) {
#pragma unroll
            for (int i = 0; i < 4; i++) {
                int idx = tid + i*128;
                int r = idx >> 4, c = idx & 15;
                cp16(s0 + a*AKV_TILE_B + r*AST + c*16, srcs[a] + (size_t)r * D_ + c*8);
            }
        }
        cp_commit();
    };
    issue(0);

    // ldmatrix lane address components
    const int lr = l & 7, lb3 = (l >> 3) & 1, lb4 = (l >> 4) & 1;
    const uint32_t q_off = (16*wid + lr + lb3*8) * AST + lb4*16;   // + ks*32
    const uint32_t k_off = (lr + lb4*8) * AST + lb3*16;            // + jj*16*AST + ks*32
    const uint32_t v_off = (lr + lb3*8) * AST + lb4*16;            // + ks2*16*AST + jj*32

    float O[16][4];
#pragma unroll
    for (int i = 0; i < 16; i++)
#pragma unroll
        for (int q = 0; q < 4; q++) O[i][q] = 0.f;
    float mrow[2] = {-1e30f, -1e30f}, lrow[2] = {0.f, 0.f};

#pragma unroll 1
    for (int kb = 0; kb < nkb; kb++) {
        cp_wait<0>();
        __syncthreads();                   // all warps done with buffer (kb-1)&1; data(kb) visible
        if (kb + 1 < nkb) issue(kb + 1);   // writes (kb+1)&1 == (kb-1)&1: safe after sync

        const uint32_t s0 = sKV + (kb & 1) * AKV_STAGE_B;
        const uint32_t sKh = s0, sKl = s0 + AKV_TILE_B;
        const uint32_t sVh = s0 + 2*AKV_TILE_B, sVl = s0 + 3*AKV_TILE_B;

        // ---- S = Q K^T (3-pass hi/lo), S is 16x32 per warp ----
        float S[4][4];
#pragma unroll
        for (int j = 0; j < 4; j++)
#pragma unroll
            for (int q = 0; q < 4; q++) S[j][q] = 0.f;

#pragma unroll
        for (int ks = 0; ks < 8; ks++) {
            uint32_t QH[4], QL[4];
            ldsm4(QH, sQh + q_off + ks*32);
            ldsm4(QL, sQl + q_off + ks*32);
#pragma unroll
            for (int jj = 0; jj < 2; jj++) {
                uint32_t KH[4], KL[4];
                ldsm4(KH, sKh + k_off + jj*(16*AST) + ks*32);
                ldsm4(KL, sKl + k_off + jj*(16*AST) + ks*32);
                mma_bf16(S[2*jj],   QH, KH[0], KH[1]);
                mma_bf16(S[2*jj],   QH, KL[0], KL[1]);
                mma_bf16(S[2*jj],   QL, KH[0], KH[1]);
                mma_bf16(S[2*jj+1], QH, KH[2], KH[3]);
                mma_bf16(S[2*jj+1], QH, KL[2], KL[3]);
                mma_bf16(S[2*jj+1], QL, KH[2], KH[3]);
            }
        }

        // ---- causal mask (last two blocks only) ----
        if (kb >= 2*qb) {
            const int row0 = q0 + 16*wid + g;
            const int cb = kb*32 + 2*t;
#pragma unroll
            for (int j = 0; j < 4; j++) {
                int c0 = cb + 8*j;
                if (c0     > row0)     S[j][0] = -1e30f;
                if (c0 + 1 > row0)     S[j][1] = -1e30f;
                if (c0     > row0 + 8) S[j][2] = -1e30f;
                if (c0 + 1 > row0 + 8) S[j][3] = -1e30f;
            }
        }

        // ---- online softmax (exp2 domain) ----
#pragma unroll
        for (int rr = 0; rr < 2; rr++) {
            float mx = -1e30f;
#pragma unroll
            for (int j = 0; j < 4; j++)
                mx = fmaxf(mx, fmaxf(S[j][2*rr], S[j][2*rr+1]));
            mx = fmaxf(mx, __shfl_xor_sync(0xffffffffu, mx, 1));
            mx = fmaxf(mx, __shfl_xor_sync(0xffffffffu, mx, 2));
            float mn = fmaxf(mrow[rr], mx);
            float corr = exp2f(mrow[rr] - mn);
            mrow[rr] = mn;
            float sum = 0.f;
#pragma unroll
            for (int j = 0; j < 4; j++) {
                float p0 = exp2f(S[j][2*rr]   - mn);
                float p1 = exp2f(S[j][2*rr+1] - mn);
                S[j][2*rr] = p0; S[j][2*rr+1] = p1;
                sum += p0 + p1;
            }
            sum += __shfl_xor_sync(0xffffffffu, sum, 1);
            sum += __shfl_xor_sync(0xffffffffu, sum, 2);
            lrow[rr] = lrow[rr]*corr + sum;
#pragma unroll
            for (int jt = 0; jt < 16; jt++) {
                O[jt][2*rr]   *= corr;
                O[jt][2*rr+1] *= corr;
            }
        }

        // ---- pack P into A-fragments (hi/lo), P is 16x32 -> 2 k16 steps ----
        uint32_t PH[2][4], PL[2][4];
#pragma unroll
        for (int ks2 = 0; ks2 < 2; ks2++) {
#pragma unroll
            for (int half = 0; half < 2; half++) {
                const int tile = 2*ks2 + half;
                split_pack(S[tile][0], S[tile][1], PH[ks2][2*half],   PL[ks2][2*half]);
                split_pack(S[tile][2], S[tile][3], PH[ks2][2*half+1], PL[ks2][2*half+1]);
            }
        }

        // ---- O += P V (3-pass hi/lo, V via ldmatrix.trans) ----
#pragma unroll
        for (int ks2 = 0; ks2 < 2; ks2++) {
#pragma unroll
            for (int jj = 0; jj < 8; jj++) {
                uint32_t VH[4], VL[4];
                ldsm4t(VH, sVh + v_off + ks2*(16*AST) + jj*32);
                ldsm4t(VL, sVl + v_off + ks2*(16*AST) + jj*32);
                mma_bf16(O[2*jj],   PH[ks2], VH[0], VH[1]);
                mma_bf16(O[2*jj],   PH[ks2], VL[0], VL[1]);
                mma_bf16(O[2*jj],   PL[ks2], VH[0], VH[1]);
                mma_bf16(O[2*jj+1], PH[ks2], VH[2], VH[3]);
                mma_bf16(O[2*jj+1], PH[ks2], VL[2], VL[3]);
                mma_bf16(O[2*jj+1], PL[ks2], VH[2], VH[3]);
            }
        }
    }

    // ---- normalize + split-write AO (bf16 hi/lo) ----
    const float inv0 = 1.f / lrow[0], inv1 = 1.f / lrow[1];
    const int r0 = q0 + 16*wid + g;
    const size_t off0 = ((size_t)(b*T_) + r0) * D_ + h * HD_ + 2*t;
#pragma unroll
    for (int jt = 0; jt < 16; jt++) {
        uint32_t hh, ll;
        split_pack(O[jt][0]*inv0, O[jt][1]*inv0, hh, ll);
        *reinterpret_cast<uint32_t*>(g_aohi + off0 + 8*jt) = hh;
        *reinterpret_cast<uint32_t*>(g_aolo + off0 + 8*jt) = ll;
        split_pack(O[jt][2]*inv1, O[jt][3]*inv1, hh, ll);
        *reinterpret_cast<uint32_t*>(g_aohi + off0 + 8*(size_t)D_ + 8*jt) = hh;
        *reinterpret_cast<uint32_t*>(g_aolo + off0 + 8*(size_t)D_ + 8*jt) = ll;
    }
}

// ---------------- launch ----------------
extern "C" void kernel_launch(void* const* d_in, const int* in_sizes, int n_in,
                              void* d_out, int out_size)
{
    (void)in_sizes; (void)n_in; (void)out_size;
    const float* x  = (const float*)d_in[0];
    const float* Wq = (const float*)d_in[1];
    const float* Wk = (const float*)d_in[2];
    const float* Wv = (const float*)d_in[3];
    const float* Wo = (const float*)d_in[4];
    const float* bo = (const float*)d_in[5];
    float* out = (float*)d_out;

    cudaFuncSetAttribute(gemm_qkv_tc, cudaFuncAttributeMaxDynamicSharedMemorySize, GSMEM_TOT);
    cudaFuncSetAttribute(gemm_out_tc, cudaFuncAttributeMaxDynamicSharedMemorySize, GSMEM_TOT);
    cudaFuncSetAttribute(attn_hmma,   cudaFuncAttributeMaxDynamicSharedMemorySize, ASMEM_TOT);

    const int n4blocks = (int)(NELEM / 4 / 256);     // 16384
    fsplit_x<<<n4blocks, 256>>>(x);
    wsplit<<<dim3(64, 64, 4), 256>>>(Wq, Wk, Wv, Wo);
    gemm_qkv_tc<<<dim3(D_/128, NTOK/128, 3), 256, GSMEM_TOT>>>();
    attn_hmma<<<2048, 128, ASMEM_TOT>>>();
    gemm_out_tc<<<dim3(D_/128, NTOK/128), 256, GSMEM_TOT>>>(bo, out);
}

// round 14
// speedup vs baseline: 1.5619x; 1.5619x over previous
#include <cuda_runtime.h>
#include <cuda_bf16.h>
#include <cstdint>

#define B_   4
#define T_   2048
#define D_   2048
#define H_   16
#define HD_  128
#define NTOK (B_*T_)
#define NELEM ((size_t)NTOK*D_)
#define WELEM ((size_t)D_*D_)

// log2(e)/sqrt(128): folded into Q so softmax uses exp2
#define QSCALE 0.12751743f

// ---------------- device scratch ----------------
__device__ __nv_bfloat16 g_xhi[NELEM];
__device__ __nv_bfloat16 g_xlo[NELEM];
__device__ __nv_bfloat16 g_qh [NELEM];
__device__ __nv_bfloat16 g_ql [NELEM];
__device__ __nv_bfloat16 g_kh [NELEM];
__device__ __nv_bfloat16 g_kl [NELEM];
__device__ __nv_bfloat16 g_vh [NELEM];
__device__ __nv_bfloat16 g_vl [NELEM];
__device__ __nv_bfloat16 g_aohi[NELEM];
__device__ __nv_bfloat16 g_aolo[NELEM];
__device__ __nv_bfloat16 g_wth[4*WELEM];   // transposed hi: [which][N][K]
__device__ __nv_bfloat16 g_wtl[4*WELEM];   // transposed lo

// ---------------- PTX helpers (compute_103-safe) ----------------
__device__ __forceinline__ uint32_t smem_u32(const void* p) {
    uint32_t a;
    asm("{ .reg .u64 t; cvta.to.shared.u64 t, %1; cvt.u32.u64 %0, t; }" : "=r"(a) : "l"(p));
    return a;
}
__device__ __forceinline__ void cp16(uint32_t sa, const void* ga) {
    asm volatile("cp.async.ca.shared.global [%0], [%1], 16;" :: "r"(sa), "l"(ga));
}
__device__ __forceinline__ void cp_commit() {
    asm volatile("cp.async.commit_group;" ::: "memory");
}
template <int N>
__device__ __forceinline__ void cp_wait() {
    asm volatile("cp.async.wait_group %0;" :: "n"(N) : "memory");
}
__device__ __forceinline__ void ldsm4(uint32_t* r, uint32_t addr) {
    asm volatile("ldmatrix.sync.aligned.m8n8.x4.shared.b16 {%0,%1,%2,%3}, [%4];"
                 : "=r"(r[0]), "=r"(r[1]), "=r"(r[2]), "=r"(r[3]) : "r"(addr));
}
__device__ __forceinline__ void ldsm4t(uint32_t* r, uint32_t addr) {
    asm volatile("ldmatrix.sync.aligned.m8n8.x4.trans.shared.b16 {%0,%1,%2,%3}, [%4];"
                 : "=r"(r[0]), "=r"(r[1]), "=r"(r[2]), "=r"(r[3]) : "r"(addr));
}
__device__ __forceinline__ void mma_bf16(float* d, const uint32_t* a, uint32_t b0, uint32_t b1) {
    asm volatile("mma.sync.aligned.m16n8k16.row.col.f32.bf16.bf16.f32 "
                 "{%0,%1,%2,%3}, {%4,%5,%6,%7}, {%8,%9}, {%0,%1,%2,%3};"
                 : "+f"(d[0]), "+f"(d[1]), "+f"(d[2]), "+f"(d[3])
                 : "r"(a[0]), "r"(a[1]), "r"(a[2]), "r"(a[3]), "r"(b0), "r"(b1));
}
// split (x,y) -> packed bf16x2 hi and lo residual (x -> low half)
__device__ __forceinline__ void split_pack(float x, float y, uint32_t& h, uint32_t& l) {
    __nv_bfloat16 hx = __float2bfloat16(x), hy = __float2bfloat16(y);
    float rx = x - __bfloat162float(hx), ry = y - __bfloat162float(hy);
    __nv_bfloat162 hh; hh.x = hx; hh.y = hy;
    __nv_bfloat162 ll = __float22bfloat162_rn(make_float2(rx, ry));
    h = *reinterpret_cast<uint32_t*>(&hh);
    l = *reinterpret_cast<uint32_t*>(&ll);
}

// ---------------- fp32 -> bf16 hi/lo split of x ----------------
__device__ __forceinline__ void split1(float v, __nv_bfloat16& h, __nv_bfloat16& l) {
    h = __float2bfloat16(v);
    l = __float2bfloat16(v - __bfloat162float(h));
}
__global__ void fsplit_x(const float* __restrict__ in) {
    size_t i = (size_t)(blockIdx.x * blockDim.x + threadIdx.x) * 4;
    float4 v = *reinterpret_cast<const float4*>(in + i);
    __nv_bfloat16 h0,h1,h2,h3,l0,l1,l2,l3;
    split1(v.x,h0,l0); split1(v.y,h1,l1); split1(v.z,h2,l2); split1(v.w,h3,l3);
    __nv_bfloat162* hp = reinterpret_cast<__nv_bfloat162*>(g_xhi + i);
    __nv_bfloat162* lp = reinterpret_cast<__nv_bfloat162*>(g_xlo + i);
    __nv_bfloat162 a; a.x=h0; a.y=h1; hp[0]=a; a.x=h2; a.y=h3; hp[1]=a;
    __nv_bfloat162 b; b.x=l0; b.y=l1; lp[0]=b; b.x=l2; b.y=l3; lp[1]=b;
}

// ---------------- weight transpose + split: W[K,N] -> Wt hi/lo [N,K] ----------------
__global__ void wsplit(const float* __restrict__ Wq, const float* __restrict__ Wk,
                       const float* __restrict__ Wv, const float* __restrict__ Wo) {
    const float* W;
    int z = blockIdx.z;
    if (z == 0) W = Wq; else if (z == 1) W = Wk; else if (z == 2) W = Wv; else W = Wo;
    __nv_bfloat16* th = g_wth + (size_t)z * WELEM;
    __nv_bfloat16* tl = g_wtl + (size_t)z * WELEM;

    __shared__ float t[32][33];
    int tx = threadIdx.x & 31, ty = threadIdx.x >> 5;   // 32 x 8
    int x0 = blockIdx.x * 32, y0 = blockIdx.y * 32;
#pragma unroll
    for (int i = 0; i < 4; i++)
        t[ty + 8*i][tx] = W[(size_t)(y0 + ty + 8*i) * D_ + x0 + tx];
    __syncthreads();
#pragma unroll
    for (int i = 0; i < 4; i++) {
        int n = x0 + ty + 8*i, k = y0 + tx;
        float v = t[tx][ty + 8*i];
        __nv_bfloat16 h, l;
        split1(v, h, l);
        th[(size_t)n * D_ + k] = h;
        tl[(size_t)n * D_ + k] = l;
    }
}

// ---------------- HMMA GEMM core (2 CTAs/SM) — R12-proven ----------------
// C[128,128] = (Ah+Al)[128,2048] @ (Bh+Bl)t ; 256 thr, 8 warps (4x2), warp 32x64.
// BK=32, stride 80B (conflict-free ldmatrix), 2-stage cp.async.
#define GST_B    80
#define GTILE_B  (128*GST_B)              // 10240
#define GSTAGE_B (4*GTILE_B)              // 40960 (Ah, Al, Bh, Bl)
#define GSMEM_TOT (2*GSTAGE_B)            // 81920 -> 2 CTAs/SM

__device__ __forceinline__
void gemm_hmma_core(const __nv_bfloat16* __restrict__ Ah, const __nv_bfloat16* __restrict__ Al,
                    const __nv_bfloat16* __restrict__ Bh, const __nv_bfloat16* __restrict__ Bl,
                    float* __restrict__ Cf, const float* __restrict__ bias,
                    __nv_bfloat16* __restrict__ oh, __nv_bfloat16* __restrict__ ol, float oscale,
                    int bx, int by)
{
    extern __shared__ char smem[];
    const uint32_t sb = smem_u32(smem);
    const int tid = threadIdx.x;
    const int wid = tid >> 5, l = tid & 31;
    const int wm = wid >> 1, wn = wid & 1;     // 4 x 2 warps, warp tile 32(m) x 64(n)
    const int m0 = by * 128, n0 = bx * 128;

    const __nv_bfloat16* src[4] = {
        Ah + (size_t)m0 * D_, Al + (size_t)m0 * D_,
        Bh + (size_t)n0 * D_, Bl + (size_t)n0 * D_ };

    // ldmatrix lane addressing
    const int a_row = (l & 7) + ((l >> 3) & 1) * 8;
    const int a_c16 = ((l >> 4) & 1) * 16;
    const int b_row = (l & 7) + ((l >> 4) & 1) * 8;
    const int b_c16 = ((l >> 3) & 1) * 16;
    uint32_t aoff[2], boff[4];
#pragma unroll
    for (int i = 0; i < 2; i++) aoff[i] = (32*wm + 16*i + a_row) * GST_B + a_c16;
#pragma unroll
    for (int p = 0; p < 4; p++) boff[p] = (64*wn + 16*p + b_row) * GST_B + b_c16;

    float d[2][8][4];
#pragma unroll
    for (int i = 0; i < 2; i++)
#pragma unroll
        for (int j = 0; j < 8; j++)
#pragma unroll
            for (int q = 0; q < 4; q++) d[i][j][q] = 0.f;

    auto issue = [&](int ch) {
        const uint32_t s0 = sb + (ch & 1) * GSTAGE_B;
        const int k0 = ch * 32;
#pragma unroll
        for (int a = 0; a < 4; a++) {
#pragma unroll
            for (int it = 0; it < 2; it++) {
                int idx = tid + it * 256;
                int row = idx >> 2, c = idx & 3;
                cp16(s0 + a*GTILE_B + row*GST_B + c*16,
                     src[a] + (size_t)row * D_ + k0 + c*8);
            }
        }
        cp_commit();
    };

    issue(0);
#pragma unroll 1
    for (int ch = 0; ch < 64; ch++) {
        if (ch < 63) { issue(ch + 1); cp_wait<1>(); }
        else         { cp_wait<0>(); }
        __syncthreads();

        const uint32_t s0 = sb + (ch & 1) * GSTAGE_B;
#pragma unroll
        for (int ks = 0; ks < 2; ks++) {
            const int kb = ks * 32;   // 16 bf16 * 2B
            uint32_t AH[2][4], AL[2][4];
#pragma unroll
            for (int i = 0; i < 2; i++) {
                ldsm4(AH[i], s0 +           aoff[i] + kb);
                ldsm4(AL[i], s0 + GTILE_B + aoff[i] + kb);
            }
#pragma unroll
            for (int p = 0; p < 4; p++) {
                uint32_t BH[4], BL[4];
                ldsm4(BH, s0 + 2*GTILE_B + boff[p] + kb);
                ldsm4(BL, s0 + 3*GTILE_B + boff[p] + kb);
#pragma unroll
                for (int i = 0; i < 2; i++) {
                    mma_bf16(d[i][2*p],   AH[i], BH[0], BH[1]);
                    mma_bf16(d[i][2*p],   AH[i], BL[0], BL[1]);
                    mma_bf16(d[i][2*p],   AL[i], BH[0], BH[1]);
                    mma_bf16(d[i][2*p+1], AH[i], BH[2], BH[3]);
                    mma_bf16(d[i][2*p+1], AH[i], BL[2], BL[3]);
                    mma_bf16(d[i][2*p+1], AL[i], BH[2], BH[3]);
                }
            }
        }
        __syncthreads();
    }

    const int gid = l >> 2, tig = l & 3;
#pragma unroll
    for (int i = 0; i < 2; i++) {
#pragma unroll
        for (int j = 0; j < 8; j++) {
            int row = m0 + 32*wm + 16*i + gid;
            int col = n0 + 64*wn + 8*j + 2*tig;
            if (Cf) {
                float2 v0 = make_float2(d[i][j][0], d[i][j][1]);
                float2 v1 = make_float2(d[i][j][2], d[i][j][3]);
                const float2 bb = *reinterpret_cast<const float2*>(bias + col);
                v0.x += bb.x; v0.y += bb.y;
                v1.x += bb.x; v1.y += bb.y;
                *reinterpret_cast<float2*>(Cf + (size_t)row * D_ + col)       = v0;
                *reinterpret_cast<float2*>(Cf + (size_t)(row + 8) * D_ + col) = v1;
            } else {
                uint32_t hh, ll;
                split_pack(d[i][j][0]*oscale, d[i][j][1]*oscale, hh, ll);
                *reinterpret_cast<uint32_t*>(oh + (size_t)row * D_ + col) = hh;
                *reinterpret_cast<uint32_t*>(ol + (size_t)row * D_ + col) = ll;
                split_pack(d[i][j][2]*oscale, d[i][j][3]*oscale, hh, ll);
                *reinterpret_cast<uint32_t*>(oh + (size_t)(row + 8) * D_ + col) = hh;
                *reinterpret_cast<uint32_t*>(ol + (size_t)(row + 8) * D_ + col) = ll;
            }
        }
    }
}

__global__ __launch_bounds__(256, 2)
void gemm_qkv_tc() {
    const int z = blockIdx.z;
    __nv_bfloat16 *oh, *ol; float sc;
    if (z == 0)      { oh = g_qh; ol = g_ql; sc = QSCALE; }
    else if (z == 1) { oh = g_kh; ol = g_kl; sc = 1.f; }
    else             { oh = g_vh; ol = g_vl; sc = 1.f; }
    gemm_hmma_core(g_xhi, g_xlo, g_wth + (size_t)z * WELEM, g_wtl + (size_t)z * WELEM,
                   nullptr, nullptr, oh, ol, sc, blockIdx.x, blockIdx.y);
}
__global__ __launch_bounds__(256, 2)
void gemm_out_tc(const float* __restrict__ bo, float* __restrict__ out) {
    gemm_hmma_core(g_aohi, g_aolo, g_wth + 3 * WELEM, g_wtl + 3 * WELEM,
                   out, bo, nullptr, nullptr, 1.f, blockIdx.x, blockIdx.y);
}

// ---------------- HMMA flash attention (causal) — R12-proven ----------------
// CTA: 128 q-rows x one head. 8 warps, warp = m16. BN=64 keys/iter.
// 2-stage cp.async KV (Kh,Kl,Vh,Vl). Softmax in fragments (exp2; scale folded into Q).
// Single sync per kb: wait -> sync -> issue(kb+1) -> compute(kb).
#define AST       272                      // smem row stride bytes (conflict-free ldmatrix)
#define AQ_TILE_B (128*AST)                // 34816
#define AKV_TILE_B (64*AST)                // 17408
#define AKV_STAGE_B (4*AKV_TILE_B)         // 69632
#define ASMEM_TOT (2*AQ_TILE_B + 2*AKV_STAGE_B)   // 208896

__global__ __launch_bounds__(256, 1)
void attn_hmma()
{
    extern __shared__ char smem[];
    const uint32_t sb = smem_u32(smem);
    const int tid = threadIdx.x;
    const int wid = tid >> 5, l = tid & 31;
    const int g = l >> 2, t = l & 3;

    const int bid = blockIdx.x;
    const int qb = 15 - (bid >> 6);        // heavy tiles first
    const int bh = bid & 63;
    const int b = bh >> 4, h = bh & 15;
    const int q0 = qb * 128;
    const int nkb = 2*qb + 2;
    const size_t qbase = ((size_t)(b*T_ + q0)) * D_ + h * HD_;
    const size_t kbase = ((size_t)(b*T_)) * D_ + h * HD_;

    const uint32_t sQh = sb, sQl = sb + AQ_TILE_B;
    const uint32_t sKV = sb + 2*AQ_TILE_B;

    // Q tiles (hi/lo) via cp.async; joins first commit group
#pragma unroll
    for (int i = 0; i < 8; i++) {
        int idx = tid + i*256;
        int r = idx >> 4, c = idx & 15;
        cp16(sQh + r*AST + c*16, g_qh + qbase + (size_t)r * D_ + c*8);
        cp16(sQl + r*AST + c*16, g_ql + qbase + (size_t)r * D_ + c*8);
    }

    auto issue = [&](int kb) {
        const uint32_t s0 = sKV + (kb & 1) * AKV_STAGE_B;
        const size_t koff = kbase + (size_t)kb * 64 * D_;
        const __nv_bfloat16* srcs[4] = { g_kh + koff, g_kl + koff, g_vh + koff, g_vl + koff };
#pragma unroll
        for (int a = 0; a < 4; a++) {
#pragma unroll
            for (int i = 0; i < 4; i++) {
                int idx = tid + i*256;
                int r = idx >> 4, c = idx & 15;
                cp16(s0 + a*AKV_TILE_B + r*AST + c*16, srcs[a] + (size_t)r * D_ + c*8);
            }
        }
        cp_commit();
    };
    issue(0);

    // ldmatrix lane address components
    const int lr = l & 7, lb3 = (l >> 3) & 1, lb4 = (l >> 4) & 1;
    const uint32_t q_off = (16*wid + lr + lb3*8) * AST + lb4*16;   // + ks*32
    const uint32_t k_off = (lr + lb4*8) * AST + lb3*16;            // + jj*16*AST + ks*32
    const uint32_t v_off = (lr + lb3*8) * AST + lb4*16;            // + ks2*16*AST + jj*32

    float O[16][4];
#pragma unroll
    for (int i = 0; i < 16; i++)
#pragma unroll
        for (int q = 0; q < 4; q++) O[i][q] = 0.f;
    float mrow[2] = {-1e30f, -1e30f}, lrow[2] = {0.f, 0.f};

#pragma unroll 1
    for (int kb = 0; kb < nkb; kb++) {
        cp_wait<0>();
        __syncthreads();                   // all warps done with buffer (kb-1)&1; data(kb) visible
        if (kb + 1 < nkb) issue(kb + 1);   // writes (kb+1)&1 == (kb-1)&1: safe after sync

        const uint32_t s0 = sKV + (kb & 1) * AKV_STAGE_B;
        const uint32_t sKh = s0, sKl = s0 + AKV_TILE_B;
        const uint32_t sVh = s0 + 2*AKV_TILE_B, sVl = s0 + 3*AKV_TILE_B;

        // ---- S = Q K^T (3-pass hi/lo) ----
        float S[8][4];
#pragma unroll
        for (int j = 0; j < 8; j++)
#pragma unroll
            for (int q = 0; q < 4; q++) S[j][q] = 0.f;

#pragma unroll
        for (int ks = 0; ks < 8; ks++) {
            uint32_t QH[4], QL[4];
            ldsm4(QH, sQh + q_off + ks*32);
            ldsm4(QL, sQl + q_off + ks*32);
#pragma unroll
            for (int jj = 0; jj < 4; jj++) {
                uint32_t KH[4], KL[4];
                ldsm4(KH, sKh + k_off + jj*(16*AST) + ks*32);
                ldsm4(KL, sKl + k_off + jj*(16*AST) + ks*32);
                mma_bf16(S[2*jj],   QH, KH[0], KH[1]);
                mma_bf16(S[2*jj],   QH, KL[0], KL[1]);
                mma_bf16(S[2*jj],   QL, KH[0], KH[1]);
                mma_bf16(S[2*jj+1], QH, KH[2], KH[3]);
                mma_bf16(S[2*jj+1], QH, KL[2], KL[3]);
                mma_bf16(S[2*jj+1], QL, KH[2], KH[3]);
            }
        }

        // ---- causal mask (last two blocks only) ----
        if (kb >= 2*qb) {
            const int row0 = q0 + 16*wid + g;
            const int cb = kb*64 + 2*t;
#pragma unroll
            for (int j = 0; j < 8; j++) {
                int c0 = cb + 8*j;
                if (c0     > row0)     S[j][0] = -1e30f;
                if (c0 + 1 > row0)     S[j][1] = -1e30f;
                if (c0     > row0 + 8) S[j][2] = -1e30f;
                if (c0 + 1 > row0 + 8) S[j][3] = -1e30f;
            }
        }

        // ---- online softmax (exp2 domain) ----
#pragma unroll
        for (int rr = 0; rr < 2; rr++) {
            float mx = -1e30f;
#pragma unroll
            for (int j = 0; j < 8; j++)
                mx = fmaxf(mx, fmaxf(S[j][2*rr], S[j][2*rr+1]));
            mx = fmaxf(mx, __shfl_xor_sync(0xffffffffu, mx, 1));
            mx = fmaxf(mx, __shfl_xor_sync(0xffffffffu, mx, 2));
            float mn = fmaxf(mrow[rr], mx);
            float corr = exp2f(mrow[rr] - mn);
            mrow[rr] = mn;
            float sum = 0.f;
#pragma unroll
            for (int j = 0; j < 8; j++) {
                float p0 = exp2f(S[j][2*rr]   - mn);
                float p1 = exp2f(S[j][2*rr+1] - mn);
                S[j][2*rr] = p0; S[j][2*rr+1] = p1;
                sum += p0 + p1;
            }
            sum += __shfl_xor_sync(0xffffffffu, sum, 1);
            sum += __shfl_xor_sync(0xffffffffu, sum, 2);
            lrow[rr] = lrow[rr]*corr + sum;
#pragma unroll
            for (int jt = 0; jt < 16; jt++) {
                O[jt][2*rr]   *= corr;
                O[jt][2*rr+1] *= corr;
            }
        }

        // ---- pack P into A-fragments (hi/lo) ----
        uint32_t PH[4][4], PL[4][4];
#pragma unroll
        for (int ks2 = 0; ks2 < 4; ks2++) {
#pragma unroll
            for (int half = 0; half < 2; half++) {
                const int tile = 2*ks2 + half;
                split_pack(S[tile][0], S[tile][1], PH[ks2][2*half],   PL[ks2][2*half]);
                split_pack(S[tile][2], S[tile][3], PH[ks2][2*half+1], PL[ks2][2*half+1]);
            }
        }

        // ---- O += P V (3-pass hi/lo, V via ldmatrix.trans) ----
#pragma unroll
        for (int ks2 = 0; ks2 < 4; ks2++) {
#pragma unroll
            for (int jj = 0; jj < 8; jj++) {
                uint32_t VH[4], VL[4];
                ldsm4t(VH, sVh + v_off + ks2*(16*AST) + jj*32);
                ldsm4t(VL, sVl + v_off + ks2*(16*AST) + jj*32);
                mma_bf16(O[2*jj],   PH[ks2], VH[0], VH[1]);
                mma_bf16(O[2*jj],   PH[ks2], VL[0], VL[1]);
                mma_bf16(O[2*jj],   PL[ks2], VH[0], VH[1]);
                mma_bf16(O[2*jj+1], PH[ks2], VH[2], VH[3]);
                mma_bf16(O[2*jj+1], PH[ks2], VL[2], VL[3]);
                mma_bf16(O[2*jj+1], PL[ks2], VH[2], VH[3]);
            }
        }
    }

    // ---- normalize + split-write AO (bf16 hi/lo) ----
    const float inv0 = 1.f / lrow[0], inv1 = 1.f / lrow[1];
    const int r0 = q0 + 16*wid + g;
    const size_t off0 = ((size_t)(b*T_) + r0) * D_ + h * HD_ + 2*t;
#pragma unroll
    for (int jt = 0; jt < 16; jt++) {
        uint32_t hh, ll;
        split_pack(O[jt][0]*inv0, O[jt][1]*inv0, hh, ll);
        *reinterpret_cast<uint32_t*>(g_aohi + off0 + 8*jt) = hh;
        *reinterpret_cast<uint32_t*>(g_aolo + off0 + 8*jt) = ll;
        split_pack(O[jt][2]*inv1, O[jt][3]*inv1, hh, ll);
        *reinterpret_cast<uint32_t*>(g_aohi + off0 + 8*(size_t)D_ + 8*jt) = hh;
        *reinterpret_cast<uint32_t*>(g_aolo + off0 + 8*(size_t)D_ + 8*jt) = ll;
    }
}

// ---------------- launch ----------------
extern "C" void kernel_launch(void* const* d_in, const int* in_sizes, int n_in,
                              void* d_out, int out_size)
{
    (void)in_sizes; (void)n_in; (void)out_size;
    const float* x  = (const float*)d_in[0];
    const float* Wq = (const float*)d_in[1];
    const float* Wk = (const float*)d_in[2];
    const float* Wv = (const float*)d_in[3];
    const float* Wo = (const float*)d_in[4];
    const float* bo = (const float*)d_in[5];
    float* out = (float*)d_out;

    cudaFuncSetAttribute(gemm_qkv_tc, cudaFuncAttributeMaxDynamicSharedMemorySize, GSMEM_TOT);
    cudaFuncSetAttribute(gemm_out_tc, cudaFuncAttributeMaxDynamicSharedMemorySize, GSMEM_TOT);
    cudaFuncSetAttribute(attn_hmma,   cudaFuncAttributeMaxDynamicSharedMemorySize, ASMEM_TOT);

    const int n4blocks = (int)(NELEM / 4 / 256);     // 16384
    fsplit_x<<<n4blocks, 256>>>(x);
    wsplit<<<dim3(64, 64, 4), 256>>>(Wq, Wk, Wv, Wo);
    gemm_qkv_tc<<<dim3(D_/128, NTOK/128, 3), 256, GSMEM_TOT>>>();
    attn_hmma<<<1024, 256, ASMEM_TOT>>>();
    gemm_out_tc<<<dim3(D_/128, NTOK/128), 256, GSMEM_TOT>>>(bo, out);
}